// round 16
// baseline (speedup 1.0000x reference)
#include <cuda_runtime.h>
#include <cuda_fp16.h>
#include <math.h>
#include <stdint.h>

// ---------------------------------------------------------------------------
// Problem constants
// ---------------------------------------------------------------------------
constexpr int B  = 8;
constexpr int S  = 1024;
constexpr int D  = 512;
constexpr int H  = 8;
constexpr int DH = 64;
constexpr int BHSD = B * H * S * DH;
constexpr int BSD  = B * S * D;

// softmax scale folded into Q plane, base-2 domain: 1/sqrt(64) * log2(e)
#define FOLD_F 0.18033688011112042f

// ---------------------------------------------------------------------------
// Device scratch (all single-plane fp16)
// ---------------------------------------------------------------------------
__device__ __half g_In16[3 * BSD];     // converted Q,K,V inputs [p][b][s][d]
__device__ __half g_Q16[BHSD];         // [bh][s][dh], fold applied
__device__ __half g_K16[BHSD];         // [bh][s][dh]
__device__ __half g_V16[BHSD];         // [bh][dh][s] (transposed)
__device__ __half g_X16[BHSD];         // attn out [bh][s][dh]

// fp16 transposed weights: [n][k] (k contiguous, ld=512)
__device__ __half g_Wt16 [3 * H * DH * D];   // proj, heads stacked n = h*64+e
__device__ __half g_Wot16[D * D];

// ---------------------------------------------------------------------------
// helpers
// ---------------------------------------------------------------------------
__device__ __forceinline__ void mma_f16(float* d, const uint32_t* a, const uint32_t* b) {
    asm volatile(
        "mma.sync.aligned.m16n8k16.row.col.f32.f16.f16.f32 "
        "{%0,%1,%2,%3}, {%4,%5,%6,%7}, {%8,%9}, {%0,%1,%2,%3};"
        : "+f"(d[0]), "+f"(d[1]), "+f"(d[2]), "+f"(d[3])
        : "r"(a[0]), "r"(a[1]), "r"(a[2]), "r"(a[3]), "r"(b[0]), "r"(b[1]));
}

__device__ __forceinline__ void ldsm4(uint32_t* r, uint32_t addr) {
    asm volatile("ldmatrix.sync.aligned.m8n8.x4.shared.b16 {%0,%1,%2,%3}, [%4];"
        : "=r"(r[0]), "=r"(r[1]), "=r"(r[2]), "=r"(r[3]) : "r"(addr));
}

__device__ __forceinline__ uint32_t ex2_pack(float a, float b) {
    __half2 h = __floats2half2_rn(a, b);
    uint32_t u = *reinterpret_cast<uint32_t*>(&h);
    uint32_t r;
    asm("ex2.approx.f16x2 %0, %1;" : "=r"(r) : "r"(u));
    return r;
}

#define CP_ASYNC16(dst_u32, gptr) \
    asm volatile("cp.async.cg.shared.global [%0], [%1], 16;" :: "r"(dst_u32), "l"(gptr))
#define CP_ASYNC_COMMIT() asm volatile("cp.async.commit_group;" ::: "memory")
#define CP_ASYNC_WAIT(n)  asm volatile("cp.async.wait_group %0;" :: "n"(n) : "memory")

__device__ __forceinline__ uint32_t pack_h2(float a, float b) {
    __half2 h = __floats2half2_rn(a, b);
    return *reinterpret_cast<uint32_t*>(&h);
}

// ---------------------------------------------------------------------------
// merged prep: input conversion (streaming) + weight transpose (strided)
// ---------------------------------------------------------------------------
constexpr int CONV_THREADS = 3 * BSD / 8;            // 1,572,864
constexpr int WT_ELEMS     = 3 * H * DH * D + D * D; // 1,048,576
constexpr int PREP_BLOCKS  = (CONV_THREADS + WT_ELEMS) / 256;

__global__ void prep_all(const float* __restrict__ Q,
                         const float* __restrict__ K,
                         const float* __restrict__ V,
                         const float* __restrict__ Wq,
                         const float* __restrict__ Wk,
                         const float* __restrict__ Wv,
                         const float* __restrict__ Wo)
{
    int i = blockIdx.x * blockDim.x + threadIdx.x;
    if (i < CONV_THREADS) {
        int p = i / (BSD / 8);
        int j = i - p * (BSD / 8);
        const float* src = (p == 0) ? Q : (p == 1) ? K : V;
        float4 a = reinterpret_cast<const float4*>(src)[j * 2];
        float4 b = reinterpret_cast<const float4*>(src)[j * 2 + 1];
        uint4 o;
        o.x = pack_h2(a.x, a.y);
        o.y = pack_h2(a.z, a.w);
        o.z = pack_h2(b.x, b.y);
        o.w = pack_h2(b.z, b.w);
        *reinterpret_cast<uint4*>(g_In16 + (size_t)p * BSD + (size_t)j * 8) = o;
    } else {
        int idx = i - CONV_THREADS;
        if (idx < 3 * H * DH * D) {
            int k = idx & 511;
            int e = (idx >> 9) & 63;
            int h = (idx >> 15) & 7;
            int p = idx >> 18;
            const float* W = (p == 0) ? Wq : (p == 1) ? Wk : Wv;
            g_Wt16[idx] = __float2half_rn(W[h * (D * DH) + k * DH + e]);
        } else {
            int j = idx - 3 * H * DH * D;
            int k = j & 511;
            int n = j >> 9;
            g_Wot16[j] = __float2half_rn(Wo[k * 512 + n]);
        }
    }
}

// ---------------------------------------------------------------------------
// fp16 cp.async GEMM, 128x128 tile (R15-proven)
// ---------------------------------------------------------------------------
constexpr int LDS_PAD = 72;
constexpr uint32_t BUF_B  = 256 * LDS_PAD * 2;    // 36864
constexpr uint32_t B_OFF  = 128 * LDS_PAD * 2;    // 18432
constexpr int GEMM_SMEM   = 2 * (int)BUF_B;       // 73728

__device__ __forceinline__ void gemm_issue16(
    const __half* __restrict__ Ap, const __half* __restrict__ Bp,
    uint32_t sbuf, int kk, int tid)
{
    #pragma unroll
    for (int i = 0; i < 4; i++) {
        int idx = tid + i * 256;
        int row = idx >> 3, cg = (idx & 7) * 8;
        uint32_t so = (uint32_t)(row * LDS_PAD + cg) * 2;
        CP_ASYNC16(sbuf + so,         Ap + (size_t)row * 512 + kk + cg);
        CP_ASYNC16(sbuf + B_OFF + so, Bp + (size_t)row * 512 + kk + cg);
    }
    CP_ASYNC_COMMIT();
}

template <int OMODE>
__device__ __forceinline__ void gemm_128x128_f16(
    const __half* __restrict__ Ap,
    const __half* __restrict__ Bp,
    const float* __restrict__ bias,
    float* __restrict__ Out, int ldOut,
    char* smem, float fold,
    __half* __restrict__ O16,
    int n0, int s0)
{
    const int tid  = threadIdx.x;
    const int wid  = tid >> 5;
    const int lane = tid & 31;
    const int g    = lane >> 2;
    const int t    = lane & 3;
    const int m0   = (wid & 3) * 32;
    const int n0w  = (wid >> 2) * 64;

    const uint32_t sbase = (uint32_t)__cvta_generic_to_shared(smem);
    const int laneRA = (lane & 7) + ((lane >> 3) & 1) * 8;
    const int laneCA = ((lane >> 4) & 1) * 8;
    const int laneRB = (lane & 7) + ((lane >> 4) & 1) * 8;
    const int laneCB = ((lane >> 3) & 1) * 8;
    uint32_t aoff[2], boff[4];
    #pragma unroll
    for (int mf = 0; mf < 2; mf++)
        aoff[mf] = (uint32_t)((m0 + mf * 16 + laneRA) * LDS_PAD + laneCA) * 2;
    #pragma unroll
    for (int nfp = 0; nfp < 4; nfp++)
        boff[nfp] = B_OFF + (uint32_t)((n0w + nfp * 16 + laneRB) * LDS_PAD + laneCB) * 2;

    float acc[2][8][4];
    #pragma unroll
    for (int mf = 0; mf < 2; mf++)
        #pragma unroll
        for (int nf = 0; nf < 8; nf++)
            #pragma unroll
            for (int r = 0; r < 4; r++) acc[mf][nf][r] = 0.f;

    gemm_issue16(Ap, Bp, sbase, 0, tid);

    for (int c = 0; c < 8; c++) {
        const int bb = c & 1;
        if (c + 1 < 8) {
            gemm_issue16(Ap, Bp, sbase + (uint32_t)(1 - bb) * BUF_B, (c + 1) * 64, tid);
            CP_ASYNC_WAIT(1);
        } else {
            CP_ASYNC_WAIT(0);
        }
        __syncthreads();

        const uint32_t su = sbase + (uint32_t)bb * BUF_B;

        #pragma unroll
        for (int ks = 0; ks < 4; ks++) {
            const uint32_t kb = (uint32_t)ks * 32;
            uint32_t ah[2][4];
            ldsm4(ah[0], su + aoff[0] + kb);
            ldsm4(ah[1], su + aoff[1] + kb);
            #pragma unroll
            for (int nfp = 0; nfp < 4; nfp++) {
                uint32_t bh4[4];
                ldsm4(bh4, su + boff[nfp] + kb);
                #pragma unroll
                for (int j = 0; j < 2; j++) {
                    const int nf = 2 * nfp + j;
                    mma_f16(acc[0][nf], ah[0], bh4 + 2 * j);
                    mma_f16(acc[1][nf], ah[1], bh4 + 2 * j);
                }
            }
        }
        __syncthreads();
    }

    // ---- epilogue ----
    if (OMODE == 0) {
        #pragma unroll
        for (int mf = 0; mf < 2; mf++) {
            #pragma unroll
            for (int nf = 0; nf < 8; nf++) {
                int row = m0 + mf * 16 + g;
                int col = n0w + nf * 8 + t * 2;
                float b0 = bias[col], b1 = bias[col + 1];
                *reinterpret_cast<float2*>(Out + (size_t)row * ldOut + col) =
                    make_float2(acc[mf][nf][0] + b0, acc[mf][nf][1] + b1);
                *reinterpret_cast<float2*>(Out + (size_t)(row + 8) * ldOut + col) =
                    make_float2(acc[mf][nf][2] + b0, acc[mf][nf][3] + b1);
            }
        }
    } else if (OMODE == 1) {
        const int head = (n0 + n0w) >> 6;
        __half* Oh = O16 + ((size_t)head * S + s0) * 64;
        #pragma unroll
        for (int mf = 0; mf < 2; mf++) {
            #pragma unroll
            for (int nf = 0; nf < 8; nf++) {
                int row = m0 + mf * 16 + g;
                int colg = n0 + n0w + nf * 8 + t * 2;
                int e = colg & 63;
                float b0 = bias[colg], b1 = bias[colg + 1];
                uint32_t h0 = pack_h2((acc[mf][nf][0] + b0) * fold,
                                      (acc[mf][nf][1] + b1) * fold);
                uint32_t h1 = pack_h2((acc[mf][nf][2] + b0) * fold,
                                      (acc[mf][nf][3] + b1) * fold);
                *reinterpret_cast<uint32_t*>(Oh + (size_t)row * 64 + e) = h0;
                *reinterpret_cast<uint32_t*>(Oh + (size_t)(row + 8) * 64 + e) = h1;
            }
        }
    } else {
        constexpr int TPAD = 136;
        __half* Ts = reinterpret_cast<__half*>(smem);
        __syncthreads();
        #pragma unroll
        for (int mf = 0; mf < 2; mf++) {
            #pragma unroll
            for (int nf = 0; nf < 8; nf++) {
                int row = m0 + mf * 16 + g;
                int col = n0w + nf * 8 + t * 2;
                int colg = n0 + col;
                float b0 = bias[colg], b1 = bias[colg + 1];
                float vv[4] = {acc[mf][nf][0] + b0, acc[mf][nf][1] + b1,
                               acc[mf][nf][2] + b0, acc[mf][nf][3] + b1};
                int rr[4] = {row, row, row + 8, row + 8};
                int cc[4] = {col, col + 1, col, col + 1};
                #pragma unroll
                for (int q = 0; q < 4; q++)
                    Ts[cc[q] * TPAD + rr[q]] = __float2half_rn(vv[q]);
            }
        }
        __syncthreads();
        for (int i = tid; i < 128 * 16; i += 256) {
            int col = i >> 4;
            int rc  = (i & 15) * 8;
            int colg = n0 + col;
            int head = colg >> 6, e = colg & 63;
            uint4 v = *reinterpret_cast<uint4*>(Ts + col * TPAD + rc);
            *reinterpret_cast<uint4*>(O16 + ((size_t)head * 64 + e) * S + s0 + rc) = v;
        }
    }
}

// ---------------------------------------------------------------------------
// QKV projection: grid (4 ntiles, 64 slabs, 3), block 256
// ---------------------------------------------------------------------------
__global__ void __launch_bounds__(256, 2)
proj_mma(const float* __restrict__ bq, const float* __restrict__ bk,
         const float* __restrict__ bv)
{
    extern __shared__ char smem[];
    const int p    = blockIdx.z;
    const int slab = blockIdx.y;
    const int b    = slab >> 3;
    const int s0   = (slab & 7) * 128;
    const int n0   = blockIdx.x * 128;

    const __half* Ap = g_In16 + (size_t)p * BSD + ((size_t)b * S + s0) * D;
    const __half* Wp = g_Wt16 + (size_t)(p * 512 + n0) * 512;
    const float* bias = (p == 0) ? bq : (p == 1) ? bk : bv;

    __half* base = ((p == 0) ? g_Q16 : (p == 1) ? g_K16 : g_V16)
                   + (size_t)b * H * S * DH;

    if (p == 0) {
        gemm_128x128_f16<1>(Ap, Wp, bias, nullptr, 0, smem, FOLD_F, base, n0, s0);
    } else if (p == 1) {
        gemm_128x128_f16<1>(Ap, Wp, bias, nullptr, 0, smem, 1.0f, base, n0, s0);
    } else {
        gemm_128x128_f16<2>(Ap, Wp, bias, nullptr, 0, smem, 1.0f, base, n0, s0);
    }
}

// ---------------------------------------------------------------------------
// Output projection: grid (4 ntiles, 8 mslabs, B), block 256
// ---------------------------------------------------------------------------
__global__ void __launch_bounds__(256, 2)
oproj_mma(const float* __restrict__ bo, float* __restrict__ out)
{
    extern __shared__ char smem[];
    const int b  = blockIdx.z;
    const int m0 = blockIdx.y * 128;
    const int n0 = blockIdx.x * 128;

    gemm_128x128_f16<0>(g_X16 + (size_t)b * 1024 * 512 + (size_t)m0 * 512,
                        g_Wot16 + (size_t)n0 * D,
                        bo + n0,
                        out + (size_t)b * 1024 * 512 + (size_t)m0 * 512 + n0,
                        512, smem, 1.0f, nullptr, 0, 0);
}

// ---------------------------------------------------------------------------
// Flash attention: fp16, Q tile 64 (4 warps), KV tile 64, 3-STAGE pipeline,
// max-free softmax, f16x2 EX2 + MMA row-sums. grid (16, 64), block 128.
// smem: 3 buffers x (K[64][72] + V[64][72]) fp16 = 55296 B.
// ---------------------------------------------------------------------------
constexpr int SPAD16   = 72;
constexpr int PLANE16  = 64 * SPAD16;
constexpr int ABUF16   = 2 * PLANE16;            // halves per buffer
constexpr int ATTN_SMEM = 3 * ABUF16 * 2;        // 55296 B

__device__ __forceinline__ void attn_issue_tile16(
    const __half* Kp, const __half* Vp,
    uint32_t sbuf, int kv0, int tid)
{
    #pragma unroll
    for (int i = 0; i < 4; i++) {
        int idx = tid + i * 128;
        int row = idx >> 3, c = (idx & 7) * 8;
        uint32_t so = (uint32_t)(row * SPAD16 + c) * 2;
        CP_ASYNC16(sbuf + so,               Kp + (size_t)(kv0 + row) * 64 + c);
        CP_ASYNC16(sbuf + PLANE16 * 2 + so, Vp + (size_t)row * S + kv0 + c);
    }
    CP_ASYNC_COMMIT();
}

__global__ void __launch_bounds__(128, 4) attn_mma()
{
    extern __shared__ __half smatt[];
    const int tid  = threadIdx.x;
    const int w    = tid >> 5;
    const int lane = tid & 31;
    const int g    = lane >> 2;
    const int t    = lane & 3;
    const int bh   = blockIdx.y;
    const int q0   = blockIdx.x * 64;
    const size_t hb = (size_t)bh * S * DH;

    const __half* Qp = g_Q16 + hb;
    const __half* Kp = g_K16 + hb;
    const __half* Vp = g_V16 + hb;
    const uint32_t sbase = (uint32_t)__cvta_generic_to_shared(smatt);

    const int laneRB = (lane & 7) + ((lane >> 4) & 1) * 8;
    const int laneCB = ((lane >> 3) & 1) * 8;
    uint32_t fragOff[4];
    #pragma unroll
    for (int nfp = 0; nfp < 4; nfp++)
        fragOff[nfp] = (uint32_t)((nfp * 16 + laneRB) * SPAD16 + laneCB) * 2;

    uint32_t qh[4][4];
    const int r0 = q0 + w * 16 + g;
    #pragma unroll
    for (int ks = 0; ks < 4; ks++) {
        int c0 = ks * 16 + 2 * t;
        qh[ks][0] = *reinterpret_cast<const uint32_t*>(Qp + (size_t)r0 * 64 + c0);
        qh[ks][1] = *reinterpret_cast<const uint32_t*>(Qp + (size_t)(r0 + 8) * 64 + c0);
        qh[ks][2] = *reinterpret_cast<const uint32_t*>(Qp + (size_t)r0 * 64 + c0 + 8);
        qh[ks][3] = *reinterpret_cast<const uint32_t*>(Qp + (size_t)(r0 + 8) * 64 + c0 + 8);
    }

    const uint32_t ONES[2] = {0x3C003C00u, 0x3C003C00u};

    float O[8][4];
    #pragma unroll
    for (int nf = 0; nf < 8; nf++)
        #pragma unroll
        for (int r = 0; r < 4; r++) O[nf][r] = 0.f;
    float ls[4] = {0.f, 0.f, 0.f, 0.f};

    // 3-stage prologue: tiles 0 and 1 in flight
    attn_issue_tile16(Kp, Vp, sbase, 0, tid);
    attn_issue_tile16(Kp, Vp, sbase + (uint32_t)ABUF16 * 2, 64, tid);

    for (int kt = 0; kt < 16; kt++) {
        const int bb = kt % 3;
        if (kt + 2 < 16) {
            attn_issue_tile16(Kp, Vp, sbase + (uint32_t)((kt + 2) % 3) * ABUF16 * 2,
                              (kt + 2) * 64, tid);
            CP_ASYNC_WAIT(2);
        } else if (kt + 1 < 16) {
            CP_ASYNC_WAIT(1);
        } else {
            CP_ASYNC_WAIT(0);
        }
        __syncthreads();

        const uint32_t sbu = sbase + (uint32_t)bb * ABUF16 * 2;

        float sc[8][4];
        #pragma unroll
        for (int nf = 0; nf < 8; nf++)
            #pragma unroll
            for (int r = 0; r < 4; r++) sc[nf][r] = 0.f;

        #pragma unroll
        for (int ks = 0; ks < 4; ks++) {
            const uint32_t kb = (uint32_t)ks * 32;
            #pragma unroll
            for (int nfp = 0; nfp < 4; nfp++) {
                uint32_t kh4[4];
                ldsm4(kh4, sbu + fragOff[nfp] + kb);
                mma_f16(sc[2 * nfp],     qh[ks], kh4);
                mma_f16(sc[2 * nfp + 1], qh[ks], kh4 + 2);
            }
        }

        uint32_t P[4][4];
        #pragma unroll
        for (int ks = 0; ks < 4; ks++) {
            P[ks][0] = ex2_pack(sc[2 * ks][0],     sc[2 * ks][1]);
            P[ks][1] = ex2_pack(sc[2 * ks][2],     sc[2 * ks][3]);
            P[ks][2] = ex2_pack(sc[2 * ks + 1][0], sc[2 * ks + 1][1]);
            P[ks][3] = ex2_pack(sc[2 * ks + 1][2], sc[2 * ks + 1][3]);
        }

        #pragma unroll
        for (int ks = 0; ks < 4; ks++)
            mma_f16(ls, P[ks], ONES);

        #pragma unroll
        for (int ks = 0; ks < 4; ks++) {
            const uint32_t kb = (uint32_t)ks * 32;
            #pragma unroll
            for (int nfp = 0; nfp < 4; nfp++) {
                uint32_t vh4[4];
                ldsm4(vh4, sbu + PLANE16 * 2 + fragOff[nfp] + kb);
                mma_f16(O[2 * nfp],     P[ks], vh4);
                mma_f16(O[2 * nfp + 1], P[ks], vh4 + 2);
            }
        }
        __syncthreads();
    }

    float ia = 1.0f / ls[0], ib = 1.0f / ls[2];
    #pragma unroll
    for (int nf = 0; nf < 8; nf++) {
        int c = nf * 8 + 2 * t;
        uint32_t h0 = pack_h2(O[nf][0] * ia, O[nf][1] * ia);
        uint32_t h1 = pack_h2(O[nf][2] * ib, O[nf][3] * ib);
        *reinterpret_cast<uint32_t*>(g_X16 + hb + (size_t)r0 * 64 + c) = h0;
        *reinterpret_cast<uint32_t*>(g_X16 + hb + (size_t)(r0 + 8) * 64 + c) = h1;
    }
}

// ---------------------------------------------------------------------------
extern "C" void kernel_launch(void* const* d_in, const int* in_sizes, int n_in,
                              void* d_out, int out_size)
{
    const float* Q  = (const float*)d_in[0];
    const float* K  = (const float*)d_in[1];
    const float* V  = (const float*)d_in[2];
    const float* Wq = (const float*)d_in[3];
    const float* bq = (const float*)d_in[4];
    const float* Wk = (const float*)d_in[5];
    const float* bk = (const float*)d_in[6];
    const float* Wv = (const float*)d_in[7];
    const float* bv = (const float*)d_in[8];
    const float* Wo = (const float*)d_in[9];
    const float* bo = (const float*)d_in[10];
    float* out = (float*)d_out;

    // 0) merged prep
    prep_all<<<PREP_BLOCKS, 256>>>(Q, K, V, Wq, Wk, Wv, Wo);

    // 1) QKV projections
    cudaFuncSetAttribute(proj_mma, cudaFuncAttributeMaxDynamicSharedMemorySize, GEMM_SMEM);
    proj_mma<<<dim3(4, 64, 3), 256, GEMM_SMEM>>>(bq, bk, bv);

    // 2) attention (3-stage pipeline)
    cudaFuncSetAttribute(attn_mma, cudaFuncAttributeMaxDynamicSharedMemorySize, ATTN_SMEM);
    attn_mma<<<dim3(S / 64, B * H), 128, ATTN_SMEM>>>();

    // 3) output projection
    cudaFuncSetAttribute(oproj_mma, cudaFuncAttributeMaxDynamicSharedMemorySize, GEMM_SMEM);
    oproj_mma<<<dim3(4, 8, B), 256, GEMM_SMEM>>>(bo, out);
}

// round 17
// speedup vs baseline: 1.0060x; 1.0060x over previous
#include <cuda_runtime.h>
#include <cuda_fp16.h>
#include <math.h>
#include <stdint.h>

// ---------------------------------------------------------------------------
// Problem constants
// ---------------------------------------------------------------------------
constexpr int B  = 8;
constexpr int S  = 1024;
constexpr int D  = 512;
constexpr int H  = 8;
constexpr int DH = 64;
constexpr int BHSD = B * H * S * DH;
constexpr int BSD  = B * S * D;

// softmax scale folded into Q plane, base-2 domain: 1/sqrt(64) * log2(e)
#define FOLD_F 0.18033688011112042f

// ---------------------------------------------------------------------------
// Device scratch (all single-plane fp16)
// ---------------------------------------------------------------------------
__device__ __half g_In16[3 * BSD];     // converted Q,K,V inputs [p][b][s][d]
__device__ __half g_Q16[BHSD];         // [bh][s][dh], fold applied
__device__ __half g_K16[BHSD];         // [bh][s][dh]
__device__ __half g_V16[BHSD];         // [bh][dh][s] (transposed)
__device__ __half g_X16[BHSD];         // attn out [bh][s][dh]

// fp16 transposed weights: [n][k] (k contiguous, ld=512)
__device__ __half g_Wt16 [3 * H * DH * D];   // proj, heads stacked n = h*64+e
__device__ __half g_Wot16[D * D];

// ---------------------------------------------------------------------------
// helpers
// ---------------------------------------------------------------------------
__device__ __forceinline__ void mma_f16(float* d, const uint32_t* a, const uint32_t* b) {
    asm volatile(
        "mma.sync.aligned.m16n8k16.row.col.f32.f16.f16.f32 "
        "{%0,%1,%2,%3}, {%4,%5,%6,%7}, {%8,%9}, {%0,%1,%2,%3};"
        : "+f"(d[0]), "+f"(d[1]), "+f"(d[2]), "+f"(d[3])
        : "r"(a[0]), "r"(a[1]), "r"(a[2]), "r"(a[3]), "r"(b[0]), "r"(b[1]));
}

__device__ __forceinline__ void ldsm4(uint32_t* r, uint32_t addr) {
    asm volatile("ldmatrix.sync.aligned.m8n8.x4.shared.b16 {%0,%1,%2,%3}, [%4];"
        : "=r"(r[0]), "=r"(r[1]), "=r"(r[2]), "=r"(r[3]) : "r"(addr));
}

__device__ __forceinline__ uint32_t ex2_pack(float a, float b) {
    __half2 h = __floats2half2_rn(a, b);
    uint32_t u = *reinterpret_cast<uint32_t*>(&h);
    uint32_t r;
    asm("ex2.approx.f16x2 %0, %1;" : "=r"(r) : "r"(u));
    return r;
}

#define CP_ASYNC16(dst_u32, gptr) \
    asm volatile("cp.async.cg.shared.global [%0], [%1], 16;" :: "r"(dst_u32), "l"(gptr))
#define CP_ASYNC_COMMIT() asm volatile("cp.async.commit_group;" ::: "memory")
#define CP_ASYNC_WAIT(n)  asm volatile("cp.async.wait_group %0;" :: "n"(n) : "memory")

__device__ __forceinline__ uint32_t pack_h2(float a, float b) {
    __half2 h = __floats2half2_rn(a, b);
    return *reinterpret_cast<uint32_t*>(&h);
}

// ---------------------------------------------------------------------------
// merged prep: input conversion (streaming) + weight transpose (strided)
// ---------------------------------------------------------------------------
constexpr int CONV_THREADS = 3 * BSD / 8;            // 1,572,864
constexpr int WT_ELEMS     = 3 * H * DH * D + D * D; // 1,048,576
constexpr int PREP_BLOCKS  = (CONV_THREADS + WT_ELEMS) / 256;

__global__ void prep_all(const float* __restrict__ Q,
                         const float* __restrict__ K,
                         const float* __restrict__ V,
                         const float* __restrict__ Wq,
                         const float* __restrict__ Wk,
                         const float* __restrict__ Wv,
                         const float* __restrict__ Wo)
{
    int i = blockIdx.x * blockDim.x + threadIdx.x;
    if (i < CONV_THREADS) {
        int p = i / (BSD / 8);
        int j = i - p * (BSD / 8);
        const float* src = (p == 0) ? Q : (p == 1) ? K : V;
        float4 a = reinterpret_cast<const float4*>(src)[j * 2];
        float4 b = reinterpret_cast<const float4*>(src)[j * 2 + 1];
        uint4 o;
        o.x = pack_h2(a.x, a.y);
        o.y = pack_h2(a.z, a.w);
        o.z = pack_h2(b.x, b.y);
        o.w = pack_h2(b.z, b.w);
        *reinterpret_cast<uint4*>(g_In16 + (size_t)p * BSD + (size_t)j * 8) = o;
    } else {
        int idx = i - CONV_THREADS;
        if (idx < 3 * H * DH * D) {
            int k = idx & 511;
            int e = (idx >> 9) & 63;
            int h = (idx >> 15) & 7;
            int p = idx >> 18;
            const float* W = (p == 0) ? Wq : (p == 1) ? Wk : Wv;
            g_Wt16[idx] = __float2half_rn(W[h * (D * DH) + k * DH + e]);
        } else {
            int j = idx - 3 * H * DH * D;
            int k = j & 511;
            int n = j >> 9;
            g_Wot16[j] = __float2half_rn(Wo[k * 512 + n]);
        }
    }
}

// ---------------------------------------------------------------------------
// fp16 cp.async GEMM, 128x128 tile, single-barrier mainloop
// ---------------------------------------------------------------------------
constexpr int LDS_PAD = 72;
constexpr uint32_t BUF_B  = 256 * LDS_PAD * 2;    // 36864
constexpr uint32_t B_OFF  = 128 * LDS_PAD * 2;    // 18432
constexpr int GEMM_SMEM   = 2 * (int)BUF_B;       // 73728

__device__ __forceinline__ void gemm_issue16(
    const __half* __restrict__ Ap, const __half* __restrict__ Bp,
    uint32_t sbuf, int kk, int tid)
{
    #pragma unroll
    for (int i = 0; i < 4; i++) {
        int idx = tid + i * 256;
        int row = idx >> 3, cg = (idx & 7) * 8;
        uint32_t so = (uint32_t)(row * LDS_PAD + cg) * 2;
        CP_ASYNC16(sbuf + so,         Ap + (size_t)row * 512 + kk + cg);
        CP_ASYNC16(sbuf + B_OFF + so, Bp + (size_t)row * 512 + kk + cg);
    }
    CP_ASYNC_COMMIT();
}

template <int OMODE>
__device__ __forceinline__ void gemm_128x128_f16(
    const __half* __restrict__ Ap,
    const __half* __restrict__ Bp,
    const float* __restrict__ bias,
    float* __restrict__ Out, int ldOut,
    char* smem, float fold,
    __half* __restrict__ O16,
    int n0, int s0)
{
    const int tid  = threadIdx.x;
    const int wid  = tid >> 5;
    const int lane = tid & 31;
    const int g    = lane >> 2;
    const int t    = lane & 3;
    const int m0   = (wid & 3) * 32;
    const int n0w  = (wid >> 2) * 64;

    const uint32_t sbase = (uint32_t)__cvta_generic_to_shared(smem);
    const int laneRA = (lane & 7) + ((lane >> 3) & 1) * 8;
    const int laneCA = ((lane >> 4) & 1) * 8;
    const int laneRB = (lane & 7) + ((lane >> 4) & 1) * 8;
    const int laneCB = ((lane >> 3) & 1) * 8;
    uint32_t aoff[2], boff[4];
    #pragma unroll
    for (int mf = 0; mf < 2; mf++)
        aoff[mf] = (uint32_t)((m0 + mf * 16 + laneRA) * LDS_PAD + laneCA) * 2;
    #pragma unroll
    for (int nfp = 0; nfp < 4; nfp++)
        boff[nfp] = B_OFF + (uint32_t)((n0w + nfp * 16 + laneRB) * LDS_PAD + laneCB) * 2;

    float acc[2][8][4];
    #pragma unroll
    for (int mf = 0; mf < 2; mf++)
        #pragma unroll
        for (int nf = 0; nf < 8; nf++)
            #pragma unroll
            for (int r = 0; r < 4; r++) acc[mf][nf][r] = 0.f;

    gemm_issue16(Ap, Bp, sbase, 0, tid);

    for (int c = 0; c < 8; c++) {
        const int bb = c & 1;
        CP_ASYNC_WAIT(0);
        __syncthreads();
        if (c + 1 < 8)
            gemm_issue16(Ap, Bp, sbase + (uint32_t)(1 - bb) * BUF_B, (c + 1) * 64, tid);

        const uint32_t su = sbase + (uint32_t)bb * BUF_B;

        #pragma unroll
        for (int ks = 0; ks < 4; ks++) {
            const uint32_t kb = (uint32_t)ks * 32;
            uint32_t ah[2][4];
            ldsm4(ah[0], su + aoff[0] + kb);
            ldsm4(ah[1], su + aoff[1] + kb);
            #pragma unroll
            for (int nfp = 0; nfp < 4; nfp++) {
                uint32_t bh4[4];
                ldsm4(bh4, su + boff[nfp] + kb);
                #pragma unroll
                for (int j = 0; j < 2; j++) {
                    const int nf = 2 * nfp + j;
                    mma_f16(acc[0][nf], ah[0], bh4 + 2 * j);
                    mma_f16(acc[1][nf], ah[1], bh4 + 2 * j);
                }
            }
        }
    }
    __syncthreads();   // before epilogue may reuse smem (OMODE 2)

    // ---- epilogue ----
    if (OMODE == 0) {
        #pragma unroll
        for (int mf = 0; mf < 2; mf++) {
            #pragma unroll
            for (int nf = 0; nf < 8; nf++) {
                int row = m0 + mf * 16 + g;
                int col = n0w + nf * 8 + t * 2;
                float b0 = bias[col], b1 = bias[col + 1];
                *reinterpret_cast<float2*>(Out + (size_t)row * ldOut + col) =
                    make_float2(acc[mf][nf][0] + b0, acc[mf][nf][1] + b1);
                *reinterpret_cast<float2*>(Out + (size_t)(row + 8) * ldOut + col) =
                    make_float2(acc[mf][nf][2] + b0, acc[mf][nf][3] + b1);
            }
        }
    } else if (OMODE == 1) {
        const int head = (n0 + n0w) >> 6;
        __half* Oh = O16 + ((size_t)head * S + s0) * 64;
        #pragma unroll
        for (int mf = 0; mf < 2; mf++) {
            #pragma unroll
            for (int nf = 0; nf < 8; nf++) {
                int row = m0 + mf * 16 + g;
                int colg = n0 + n0w + nf * 8 + t * 2;
                int e = colg & 63;
                float b0 = bias[colg], b1 = bias[colg + 1];
                uint32_t h0 = pack_h2((acc[mf][nf][0] + b0) * fold,
                                      (acc[mf][nf][1] + b1) * fold);
                uint32_t h1 = pack_h2((acc[mf][nf][2] + b0) * fold,
                                      (acc[mf][nf][3] + b1) * fold);
                *reinterpret_cast<uint32_t*>(Oh + (size_t)row * 64 + e) = h0;
                *reinterpret_cast<uint32_t*>(Oh + (size_t)(row + 8) * 64 + e) = h1;
            }
        }
    } else {
        constexpr int TPAD = 136;
        __half* Ts = reinterpret_cast<__half*>(smem);
        #pragma unroll
        for (int mf = 0; mf < 2; mf++) {
            #pragma unroll
            for (int nf = 0; nf < 8; nf++) {
                int row = m0 + mf * 16 + g;
                int col = n0w + nf * 8 + t * 2;
                int colg = n0 + col;
                float b0 = bias[colg], b1 = bias[colg + 1];
                float vv[4] = {acc[mf][nf][0] + b0, acc[mf][nf][1] + b1,
                               acc[mf][nf][2] + b0, acc[mf][nf][3] + b1};
                int rr[4] = {row, row, row + 8, row + 8};
                int cc[4] = {col, col + 1, col, col + 1};
                #pragma unroll
                for (int q = 0; q < 4; q++)
                    Ts[cc[q] * TPAD + rr[q]] = __float2half_rn(vv[q]);
            }
        }
        __syncthreads();
        for (int i = tid; i < 128 * 16; i += 256) {
            int col = i >> 4;
            int rc  = (i & 15) * 8;
            int colg = n0 + col;
            int head = colg >> 6, e = colg & 63;
            uint4 v = *reinterpret_cast<uint4*>(Ts + col * TPAD + rc);
            *reinterpret_cast<uint4*>(O16 + ((size_t)head * 64 + e) * S + s0 + rc) = v;
        }
    }
}

// ---------------------------------------------------------------------------
// QKV projection: grid (4 ntiles, 64 slabs, 3), block 256
// ---------------------------------------------------------------------------
__global__ void __launch_bounds__(256, 2)
proj_mma(const float* __restrict__ bq, const float* __restrict__ bk,
         const float* __restrict__ bv)
{
    extern __shared__ char smem[];
    const int p    = blockIdx.z;
    const int slab = blockIdx.y;
    const int b    = slab >> 3;
    const int s0   = (slab & 7) * 128;
    const int n0   = blockIdx.x * 128;

    const __half* Ap = g_In16 + (size_t)p * BSD + ((size_t)b * S + s0) * D;
    const __half* Wp = g_Wt16 + (size_t)(p * 512 + n0) * 512;
    const float* bias = (p == 0) ? bq : (p == 1) ? bk : bv;

    __half* base = ((p == 0) ? g_Q16 : (p == 1) ? g_K16 : g_V16)
                   + (size_t)b * H * S * DH;

    if (p == 0) {
        gemm_128x128_f16<1>(Ap, Wp, bias, nullptr, 0, smem, FOLD_F, base, n0, s0);
    } else if (p == 1) {
        gemm_128x128_f16<1>(Ap, Wp, bias, nullptr, 0, smem, 1.0f, base, n0, s0);
    } else {
        gemm_128x128_f16<2>(Ap, Wp, bias, nullptr, 0, smem, 1.0f, base, n0, s0);
    }
}

// ---------------------------------------------------------------------------
// Output projection: grid (4 ntiles, 8 mslabs, B), block 256
// ---------------------------------------------------------------------------
__global__ void __launch_bounds__(256, 2)
oproj_mma(const float* __restrict__ bo, float* __restrict__ out)
{
    extern __shared__ char smem[];
    const int b  = blockIdx.z;
    const int m0 = blockIdx.y * 128;
    const int n0 = blockIdx.x * 128;

    gemm_128x128_f16<0>(g_X16 + (size_t)b * 1024 * 512 + (size_t)m0 * 512,
                        g_Wot16 + (size_t)n0 * D,
                        bo + n0,
                        out + (size_t)b * 1024 * 512 + (size_t)m0 * 512 + n0,
                        512, smem, 1.0f, nullptr, 0, 0);
}

// ---------------------------------------------------------------------------
// Flash attention: fp16, Q tile 64 (4 warps), KV tile 64, 3-stage pipeline,
// SINGLE barrier per tile. grid (16, 64), block 128.
// smem: 3 buffers x (K[64][72] + V[64][72]) fp16 = 55296 B.
// ---------------------------------------------------------------------------
constexpr int SPAD16   = 72;
constexpr int PLANE16  = 64 * SPAD16;
constexpr int ABUF16   = 2 * PLANE16;
constexpr int ATTN_SMEM = 3 * ABUF16 * 2;        // 55296 B

__device__ __forceinline__ void attn_issue_tile16(
    const __half* Kp, const __half* Vp,
    uint32_t sbuf, int kv0, int tid)
{
    #pragma unroll
    for (int i = 0; i < 4; i++) {
        int idx = tid + i * 128;
        int row = idx >> 3, c = (idx & 7) * 8;
        uint32_t so = (uint32_t)(row * SPAD16 + c) * 2;
        CP_ASYNC16(sbuf + so,               Kp + (size_t)(kv0 + row) * 64 + c);
        CP_ASYNC16(sbuf + PLANE16 * 2 + so, Vp + (size_t)row * S + kv0 + c);
    }
    CP_ASYNC_COMMIT();
}

__global__ void __launch_bounds__(128, 4) attn_mma()
{
    extern __shared__ __half smatt[];
    const int tid  = threadIdx.x;
    const int w    = tid >> 5;
    const int lane = tid & 31;
    const int g    = lane >> 2;
    const int t    = lane & 3;
    const int bh   = blockIdx.y;
    const int q0   = blockIdx.x * 64;
    const size_t hb = (size_t)bh * S * DH;

    const __half* Qp = g_Q16 + hb;
    const __half* Kp = g_K16 + hb;
    const __half* Vp = g_V16 + hb;
    const uint32_t sbase = (uint32_t)__cvta_generic_to_shared(smatt);

    const int laneRB = (lane & 7) + ((lane >> 4) & 1) * 8;
    const int laneCB = ((lane >> 3) & 1) * 8;
    uint32_t fragOff[4];
    #pragma unroll
    for (int nfp = 0; nfp < 4; nfp++)
        fragOff[nfp] = (uint32_t)((nfp * 16 + laneRB) * SPAD16 + laneCB) * 2;

    uint32_t qh[4][4];
    const int r0 = q0 + w * 16 + g;
    #pragma unroll
    for (int ks = 0; ks < 4; ks++) {
        int c0 = ks * 16 + 2 * t;
        qh[ks][0] = *reinterpret_cast<const uint32_t*>(Qp + (size_t)r0 * 64 + c0);
        qh[ks][1] = *reinterpret_cast<const uint32_t*>(Qp + (size_t)(r0 + 8) * 64 + c0);
        qh[ks][2] = *reinterpret_cast<const uint32_t*>(Qp + (size_t)r0 * 64 + c0 + 8);
        qh[ks][3] = *reinterpret_cast<const uint32_t*>(Qp + (size_t)(r0 + 8) * 64 + c0 + 8);
    }

    const uint32_t ONES[2] = {0x3C003C00u, 0x3C003C00u};

    float O[8][4];
    #pragma unroll
    for (int nf = 0; nf < 8; nf++)
        #pragma unroll
        for (int r = 0; r < 4; r++) O[nf][r] = 0.f;
    float ls[4] = {0.f, 0.f, 0.f, 0.f};

    // prologue: tiles 0 and 1 in flight
    attn_issue_tile16(Kp, Vp, sbase, 0, tid);
    attn_issue_tile16(Kp, Vp, sbase + (uint32_t)ABUF16 * 2, 64, tid);

    for (int kt = 0; kt < 16; kt++) {
        const int bb = kt % 3;
        if (kt < 15) { CP_ASYNC_WAIT(1); } else { CP_ASYNC_WAIT(0); }
        __syncthreads();
        if (kt + 2 < 16)
            attn_issue_tile16(Kp, Vp, sbase + (uint32_t)((kt + 2) % 3) * ABUF16 * 2,
                              (kt + 2) * 64, tid);

        const uint32_t sbu = sbase + (uint32_t)bb * ABUF16 * 2;

        float sc[8][4];
        #pragma unroll
        for (int nf = 0; nf < 8; nf++)
            #pragma unroll
            for (int r = 0; r < 4; r++) sc[nf][r] = 0.f;

        #pragma unroll
        for (int ks = 0; ks < 4; ks++) {
            const uint32_t kb = (uint32_t)ks * 32;
            #pragma unroll
            for (int nfp = 0; nfp < 4; nfp++) {
                uint32_t kh4[4];
                ldsm4(kh4, sbu + fragOff[nfp] + kb);
                mma_f16(sc[2 * nfp],     qh[ks], kh4);
                mma_f16(sc[2 * nfp + 1], qh[ks], kh4 + 2);
            }
        }

        uint32_t P[4][4];
        #pragma unroll
        for (int ks = 0; ks < 4; ks++) {
            P[ks][0] = ex2_pack(sc[2 * ks][0],     sc[2 * ks][1]);
            P[ks][1] = ex2_pack(sc[2 * ks][2],     sc[2 * ks][3]);
            P[ks][2] = ex2_pack(sc[2 * ks + 1][0], sc[2 * ks + 1][1]);
            P[ks][3] = ex2_pack(sc[2 * ks + 1][2], sc[2 * ks + 1][3]);
        }

        #pragma unroll
        for (int ks = 0; ks < 4; ks++)
            mma_f16(ls, P[ks], ONES);

        #pragma unroll
        for (int ks = 0; ks < 4; ks++) {
            const uint32_t kb = (uint32_t)ks * 32;
            #pragma unroll
            for (int nfp = 0; nfp < 4; nfp++) {
                uint32_t vh4[4];
                ldsm4(vh4, sbu + PLANE16 * 2 + fragOff[nfp] + kb);
                mma_f16(O[2 * nfp],     P[ks], vh4);
                mma_f16(O[2 * nfp + 1], P[ks], vh4 + 2);
            }
        }
    }

    float ia = 1.0f / ls[0], ib = 1.0f / ls[2];
    #pragma unroll
    for (int nf = 0; nf < 8; nf++) {
        int c = nf * 8 + 2 * t;
        uint32_t h0 = pack_h2(O[nf][0] * ia, O[nf][1] * ia);
        uint32_t h1 = pack_h2(O[nf][2] * ib, O[nf][3] * ib);
        *reinterpret_cast<uint32_t*>(g_X16 + hb + (size_t)r0 * 64 + c) = h0;
        *reinterpret_cast<uint32_t*>(g_X16 + hb + (size_t)(r0 + 8) * 64 + c) = h1;
    }
}

// ---------------------------------------------------------------------------
extern "C" void kernel_launch(void* const* d_in, const int* in_sizes, int n_in,
                              void* d_out, int out_size)
{
    const float* Q  = (const float*)d_in[0];
    const float* K  = (const float*)d_in[1];
    const float* V  = (const float*)d_in[2];
    const float* Wq = (const float*)d_in[3];
    const float* bq = (const float*)d_in[4];
    const float* Wk = (const float*)d_in[5];
    const float* bk = (const float*)d_in[6];
    const float* Wv = (const float*)d_in[7];
    const float* bv = (const float*)d_in[8];
    const float* Wo = (const float*)d_in[9];
    const float* bo = (const float*)d_in[10];
    float* out = (float*)d_out;

    // 0) merged prep
    prep_all<<<PREP_BLOCKS, 256>>>(Q, K, V, Wq, Wk, Wv, Wo);

    // 1) QKV projections (single-barrier mainloop)
    cudaFuncSetAttribute(proj_mma, cudaFuncAttributeMaxDynamicSharedMemorySize, GEMM_SMEM);
    proj_mma<<<dim3(4, 64, 3), 256, GEMM_SMEM>>>(bq, bk, bv);

    // 2) attention (single-barrier 3-stage pipeline)
    cudaFuncSetAttribute(attn_mma, cudaFuncAttributeMaxDynamicSharedMemorySize, ATTN_SMEM);
    attn_mma<<<dim3(S / 64, B * H), 128, ATTN_SMEM>>>();

    // 3) output projection (single-barrier mainloop)
    cudaFuncSetAttribute(oproj_mma, cudaFuncAttributeMaxDynamicSharedMemorySize, GEMM_SMEM);
    oproj_mma<<<dim3(4, 8, B), 256, GEMM_SMEM>>>(bo, out);
}